// round 15
// baseline (speedup 1.0000x reference)
#include <cuda_runtime.h>
#include <cuda_fp16.h>
#include <cstdint>
#include <cstddef>

#define N_NODES 50000
#define N_EDGES 800000
#define HID 512
#define NB_ROW 391            // ceil(50000/128)
#define NB_NODE (NB_ROW * 4)  // 1564 node tiles (3 stages, K=192)
#define NB_UV   (NB_ROW * 8)  // 3128 uv tiles (1 stage, K=64)
#define GRID_GEMM (NB_NODE + NB_UV)
#define NB_EDGE 50000         // 400000 edge pairs / 8 warps per block
#define SMEM_BYTES (2 * 64 * 132 * 4)   // gemm As + Bs, 67584 B

typedef unsigned long long ull;

// Scratch (device globals; no allocation allowed)
__device__ __align__(32) __half g_Uh[(size_t)N_NODES * HID];
__device__ __align__(32) __half g_Vh[(size_t)N_NODES * HID];
__device__ __align__(16) float  g_Wc[64 * HID];   // W1 + W2
__device__ __align__(16) float  g_c0[HID];
__device__ __align__(16) float  g_c1[HID];
__device__ int g_idx64;

__device__ __forceinline__ ull dup2(float x) {
    ull r; asm("mov.b64 %0, {%1,%1};" : "=l"(r) : "f"(x)); return r;
}
__device__ __forceinline__ void unpack2(ull p, float& x, float& y) {
    asm("mov.b64 {%0,%1}, %2;" : "=f"(x), "=f"(y) : "l"(p));
}
#define FFMA2(d, a, b, c) \
    asm("fma.rn.f32x2 %0, %1, %2, %3;" : "=l"(d) : "l"(a), "l"(b), "l"(c))

// 256-bit gather load with L2 evict_last (only legal width for the hint).
struct U8 { unsigned r[8]; };
__device__ __forceinline__ U8 ldg256_el(const void* p) {
    U8 v;
    asm("ld.global.nc.L2::evict_last.v8.b32 {%0,%1,%2,%3,%4,%5,%6,%7}, [%8];"
        : "=r"(v.r[0]), "=r"(v.r[1]), "=r"(v.r[2]), "=r"(v.r[3]),
          "=r"(v.r[4]), "=r"(v.r[5]), "=r"(v.r[6]), "=r"(v.r[7])
        : "l"(p));
    return v;
}

// ---------------------------------------------------------------------------
// Prep: blocks 0..31 -> Wc; 32..47 -> c0/c1 (parallel k-reduction);
//       block 48 -> idx64 detect.
// ---------------------------------------------------------------------------
__global__ void prep_kernel(const float* __restrict__ ef,
                            const float* __restrict__ tte,
                            const float* __restrict__ W,
                            const float* __restrict__ b,
                            const int* __restrict__ ei) {
    const int bi = blockIdx.x, tid = threadIdx.x;
    if (bi < 32) {
        int i = bi * 256 + tid;              // 8192 float4
        float4 a = __ldg((const float4*)(W + 128 * HID) + i);
        float4 c = __ldg((const float4*)(W + 192 * HID) + i);
        a.x += c.x; a.y += c.y; a.z += c.z; a.w += c.w;
        ((float4*)g_Wc)[i] = a;
    } else if (bi < 48) {
        __shared__ float sm0[8][32], sm1[8][32];
        const int kc = tid >> 5, jl = tid & 31;
        const int j0 = (bi - 32) * 32;
        const int j = j0 + jl;
        float s0 = 0.f, s1 = 0.f;
        #pragma unroll 4
        for (int k = kc * 16; k < kc * 16 + 16; k++) {
            float w3 = __ldg(&W[(size_t)(256 + k) * HID + j]);
            s0 += tte[k] * w3;
            s1 += tte[128 + k] * w3 + ef[k] * __ldg(&W[(size_t)k * HID + j]);
        }
        sm0[kc][jl] = s0;
        sm1[kc][jl] = s1;
        __syncthreads();
        if (tid < 32) {
            float a0 = b[j0 + tid], a1 = a0;
            #pragma unroll
            for (int q = 0; q < 8; q++) { a0 += sm0[q][tid]; a1 += sm1[q][tid]; }
            g_c0[j0 + tid] = a0;
            g_c1[j0 + tid] = a1;
        }
    } else if (tid == 0) {
        int is64 = 1;
        #pragma unroll
        for (int i = 1; i < 64; i += 2)
            if (ei[i] != 0) is64 = 0;
        g_idx64 = is64;
    }
}

// ---------------------------------------------------------------------------
// Merged GEMM (R12 measured-best). 128x128 tile, BK=64, 256 threads,
// 8x8/thread, f32x2. Warp shape 8 tx x 4 ty -> conflict-free LDS.
// ---------------------------------------------------------------------------
__global__ void __launch_bounds__(256, 2)
gemm_kernel(const float* __restrict__ nf, const float* __restrict__ pe,
            const float* __restrict__ W, float* __restrict__ out) {
    extern __shared__ float smem_dyn[];
    float* As = smem_dyn;              // [64][132]
    float* Bs = smem_dyn + 64 * 132;   // [64][132]

    const int tid = threadIdx.x;
    const int lane_ = tid & 31, wid_ = tid >> 5;
    const int tx8 = (((wid_ & 1) << 3) + (lane_ & 7)) * 8;
    const int ty8 = (((wid_ >> 1) << 2) + (lane_ >> 3)) * 8;
    const int n4a = tx8 >> 2;
    const int n4b = n4a + 1;
    const char* bbA = (const char*)&Bs[(n4a ^ ((n4a >> 3) & 1)) << 2];
    const char* bbB = (const char*)&Bs[(n4b ^ ((n4b >> 3) & 1)) << 2];

    const int bi = blockIdx.x;
    int row0, col0, nstages, is_node, uv = 0;
    if (bi < NB_NODE) {
        is_node = 1;
        row0 = (bi >> 2) * 128;
        col0 = (bi & 3) * 128;
        nstages = 3;
    } else {
        is_node = 0;
        int u = bi - NB_NODE;
        row0 = (u >> 3) * 128;
        uv   = (u & 7) >> 2;
        col0 = (u & 3) * 128;
        nstages = 1;
    }

    ull acc[32];
    #pragma unroll
    for (int i = 0; i < 32; i++) acc[i] = 0ull;

    for (int s = 0; s < nstages; s++) {
        const float* Asrc; int L, kcol0;
        const float* Bsrc;
        if (!is_node) {
            Asrc = pe; L = 64; kcol0 = 0;
            Bsrc = W + (size_t)(128 + 64 * uv) * HID + col0;
        } else if (s < 2) {
            Asrc = nf; L = 128; kcol0 = s * 64;
            Bsrc = W + (size_t)(s * 64) * HID + col0;
        } else {
            Asrc = pe; L = 64; kcol0 = 0;
            Bsrc = g_Wc + col0;
        }

        #pragma unroll
        for (int i = 0; i < 8; i++) {
            int idx = i * 256 + tid;
            int m = idx >> 4, kq = idx & 15;
            int r = row0 + m;
            float4 v = (r < N_NODES)
                ? __ldg((const float4*)(Asrc + (size_t)r * L + kcol0) + kq)
                : make_float4(0.f, 0.f, 0.f, 0.f);
            int ms = m ^ (kq << 2);
            As[(kq * 4 + 0) * 132 + ms] = v.x;
            As[(kq * 4 + 1) * 132 + ms] = v.y;
            As[(kq * 4 + 2) * 132 + ms] = v.z;
            As[(kq * 4 + 3) * 132 + ms] = v.w;
        }
        #pragma unroll
        for (int i = 0; i < 8; i++) {
            int idx = i * 256 + tid;
            int k = idx >> 5, n4 = idx & 31;
            float4 v = __ldg((const float4*)(Bsrc + (size_t)k * HID) + n4);
            *(float4*)&Bs[k * 132 + ((n4 ^ ((n4 >> 3) & 1)) << 2)] = v;
        }
        __syncthreads();

        #pragma unroll
        for (int kq = 0; kq < 16; kq++) {
            const int x = kq << 2;
            const float* ar0 = &As[ty8 ^ x];
            const float* ar1 = &As[(ty8 + 4) ^ x];
            #pragma unroll
            for (int kk = 0; kk < 4; kk++) {
                const int k = kq * 4 + kk;
                const float4 a0 = *(const float4*)(ar0 + k * 132);
                const float4 a1 = *(const float4*)(ar1 + k * 132);
                const ulonglong2 B0 = *(const ulonglong2*)(bbA + (size_t)k * 528);
                const ulonglong2 B1 = *(const ulonglong2*)(bbB + (size_t)k * 528);
                ull aa;
                aa = dup2(a0.x);
                FFMA2(acc[ 0], aa, B0.x, acc[ 0]); FFMA2(acc[ 1], aa, B0.y, acc[ 1]);
                FFMA2(acc[ 2], aa, B1.x, acc[ 2]); FFMA2(acc[ 3], aa, B1.y, acc[ 3]);
                aa = dup2(a0.y);
                FFMA2(acc[ 4], aa, B0.x, acc[ 4]); FFMA2(acc[ 5], aa, B0.y, acc[ 5]);
                FFMA2(acc[ 6], aa, B1.x, acc[ 6]); FFMA2(acc[ 7], aa, B1.y, acc[ 7]);
                aa = dup2(a0.z);
                FFMA2(acc[ 8], aa, B0.x, acc[ 8]); FFMA2(acc[ 9], aa, B0.y, acc[ 9]);
                FFMA2(acc[10], aa, B1.x, acc[10]); FFMA2(acc[11], aa, B1.y, acc[11]);
                aa = dup2(a0.w);
                FFMA2(acc[12], aa, B0.x, acc[12]); FFMA2(acc[13], aa, B0.y, acc[13]);
                FFMA2(acc[14], aa, B1.x, acc[14]); FFMA2(acc[15], aa, B1.y, acc[15]);
                aa = dup2(a1.x);
                FFMA2(acc[16], aa, B0.x, acc[16]); FFMA2(acc[17], aa, B0.y, acc[17]);
                FFMA2(acc[18], aa, B1.x, acc[18]); FFMA2(acc[19], aa, B1.y, acc[19]);
                aa = dup2(a1.y);
                FFMA2(acc[20], aa, B0.x, acc[20]); FFMA2(acc[21], aa, B0.y, acc[21]);
                FFMA2(acc[22], aa, B1.x, acc[22]); FFMA2(acc[23], aa, B1.y, acc[23]);
                aa = dup2(a1.z);
                FFMA2(acc[24], aa, B0.x, acc[24]); FFMA2(acc[25], aa, B0.y, acc[25]);
                FFMA2(acc[26], aa, B1.x, acc[26]); FFMA2(acc[27], aa, B1.y, acc[27]);
                aa = dup2(a1.w);
                FFMA2(acc[28], aa, B0.x, acc[28]); FFMA2(acc[29], aa, B0.y, acc[29]);
                FFMA2(acc[30], aa, B1.x, acc[30]); FFMA2(acc[31], aa, B1.y, acc[31]);
            }
        }
        if (s + 1 < nstages) __syncthreads();
    }

    if (!is_node) {
        __half* Out = uv ? g_Vh : g_Uh;
        #pragma unroll
        for (int m = 0; m < 8; m++) {
            int r = row0 + ty8 + m;
            if (r < N_NODES) {
                float f0, f1, f2, f3, f4, f5, f6, f7;
                unpack2(acc[m * 4 + 0], f0, f1);
                unpack2(acc[m * 4 + 1], f2, f3);
                unpack2(acc[m * 4 + 2], f4, f5);
                unpack2(acc[m * 4 + 3], f6, f7);
                uint4 pk;
                __half2* ph = (__half2*)&pk;
                ph[0] = __floats2half2_rn(f0, f1);
                ph[1] = __floats2half2_rn(f2, f3);
                ph[2] = __floats2half2_rn(f4, f5);
                ph[3] = __floats2half2_rn(f6, f7);
                *(uint4*)(Out + (size_t)r * HID + col0 + tx8) = pk;
            }
        }
    } else {
        const float4 cA = *(const float4*)&g_c0[col0 + tx8];
        const float4 cB = *(const float4*)&g_c0[col0 + tx8 + 4];
        #pragma unroll
        for (int m = 0; m < 8; m++) {
            int r = row0 + ty8 + m;
            if (r < N_NODES) {
                float4 o0, o1;
                unpack2(acc[m * 4 + 0], o0.x, o0.y);
                unpack2(acc[m * 4 + 1], o0.z, o0.w);
                unpack2(acc[m * 4 + 2], o1.x, o1.y);
                unpack2(acc[m * 4 + 3], o1.z, o1.w);
                o0.x += cA.x; o0.y += cA.y; o0.z += cA.z; o0.w += cA.w;
                o1.x += cB.x; o1.y += cB.y; o1.z += cB.z; o1.w += cB.w;
                float* dst = out + (size_t)r * HID + col0 + tx8;
                __stcs((float4*)dst, o0);
                __stcs((float4*)(dst + 4), o1);
            }
        }
    }
}

// ---------------------------------------------------------------------------
// Edge rows, COLUMN-HALF pass: out[N+e][col0:col0+256] = Uh[s][half] +
// Vh[d][half] + c1[half]. One warp per edge pair; lanes 0-15 cover e0,
// lanes 16-31 cover e1, so ONE v8 evict_last load per matrix serves both.
// Per pass the gather working set is 51 MB (fits L2 beside the write
// stream). Stores via smem swizzle f^(f>>2) -> contiguous 512B slabs.
// ---------------------------------------------------------------------------
__global__ void __launch_bounds__(256)
edge_kernel(const int* __restrict__ ei, float* __restrict__ out,
            const int col0) {
    __shared__ float4 sbuf[8][128];     // 2KB per warp (2 edges x 64 float4)
    const int tid = threadIdx.x;
    const int w = tid >> 5, c = tid & 31;
    const int p = blockIdx.x * 8 + w;   // edge pair < 400000
    const int e0 = p * 2, e1 = e0 + 1;

    int s0, d0, s1, d1;
    if (g_idx64) {
        s0 = ei[2 * (size_t)e0];
        d0 = ei[2 * ((size_t)N_EDGES + e0)];
        s1 = ei[2 * (size_t)e1];
        d1 = ei[2 * ((size_t)N_EDGES + e1)];
    } else {
        s0 = ei[e0];  d0 = ei[N_EDGES + e0];
        s1 = ei[e1];  d1 = ei[N_EDGES + e1];
    }

    const int cl = c & 15;                       // lane within edge
    const int sI = (c < 16) ? s0 : s1;
    const int dI = (c < 16) ? d0 : d1;
    const size_t hoff = (size_t)col0 + cl * 16;  // halves within row

    U8 u = ldg256_el(g_Uh + (size_t)sI * HID + hoff);
    U8 v = ldg256_el(g_Vh + (size_t)dI * HID + hoff);

    // c1 slice: floats [col0 + 16*cl, +16)
    float4 c1r[4];
    #pragma unroll
    for (int j = 0; j < 4; j++)
        c1r[j] = __ldg((const float4*)(g_c1 + col0 + cl * 16) + j);

    // compute + stage: f = c*4+j  (e0 occupies f 0..63, e1 f 64..127)
    #pragma unroll
    for (int j = 0; j < 4; j++) {
        float2 ua = __half22float2(*(const __half2*)&u.r[j * 2]);
        float2 ub = __half22float2(*(const __half2*)&u.r[j * 2 + 1]);
        float2 va = __half22float2(*(const __half2*)&v.r[j * 2]);
        float2 vb = __half22float2(*(const __half2*)&v.r[j * 2 + 1]);
        float4 o;
        o.x = ua.x + va.x + c1r[j].x;  o.y = ua.y + va.y + c1r[j].y;
        o.z = ub.x + vb.x + c1r[j].z;  o.w = ub.y + vb.y + c1r[j].w;
        int f = c * 4 + j;
        sbuf[w][f ^ (f >> 2)] = o;
    }
    __syncwarp();

    // store: q<2 -> e0, q>=2 -> e1; each instr = contiguous 512B slab
    float4* dst0 = (float4*)(out + (size_t)(N_NODES + e0) * HID + col0);
    float4* dst1 = (float4*)(out + (size_t)(N_NODES + e1) * HID + col0);
    #pragma unroll
    for (int q = 0; q < 4; q++) {
        int f = q * 32 + c;
        float4 val = sbuf[w][f ^ (f >> 2)];
        float4* dst = (q < 2) ? dst0 : dst1;
        __stcs(dst + (q & 1) * 32 + c, val);
    }
}

// ---------------------------------------------------------------------------
static bool g_attr_set = false;

extern "C" void kernel_launch(void* const* d_in, const int* in_sizes, int n_in,
                              void* d_out, int out_size) {
    const void* ptr[7] = {d_in[0], d_in[1], d_in[2], d_in[3], d_in[4], d_in[5], d_in[6]};
    const int want[7] = {6400000, 3200000, 128, 256, 196608, 512, 1600000};
    const void* mapped[7];
    for (int w = 0; w < 7; w++) {
        mapped[w] = ptr[w < n_in ? w : 0];
        for (int i = 0; i < n_in && i < 7; i++)
            if (in_sizes[i] == want[w]) { mapped[w] = ptr[i]; break; }
    }
    const float* nf  = (const float*)mapped[0];
    const float* pe  = (const float*)mapped[1];
    const float* ef  = (const float*)mapped[2];
    const float* tte = (const float*)mapped[3];
    const float* W   = (const float*)mapped[4];
    const float* b   = (const float*)mapped[5];
    const int*   ei  = (const int*)mapped[6];
    float* out = (float*)d_out;

    if (!g_attr_set) {
        cudaStreamCaptureStatus cs = cudaStreamCaptureStatusNone;
        cudaStreamIsCapturing((cudaStream_t)0, &cs);
        if (cs == cudaStreamCaptureStatusNone) {
            cudaFuncSetAttribute(gemm_kernel,
                                 cudaFuncAttributeMaxDynamicSharedMemorySize,
                                 SMEM_BYTES);
            g_attr_set = true;
        }
    }

    prep_kernel<<<49, 256>>>(ef, tte, W, b, ei);
    gemm_kernel<<<GRID_GEMM, 256, SMEM_BYTES>>>(nf, pe, W, out);
    edge_kernel<<<NB_EDGE, 256>>>(ei, out, 0);     // cols   0..255
    edge_kernel<<<NB_EDGE, 256>>>(ei, out, 256);   // cols 256..511
}

// round 16
// speedup vs baseline: 1.1230x; 1.1230x over previous
#include <cuda_runtime.h>
#include <cuda_fp16.h>
#include <cstdint>
#include <cstddef>

#define N_NODES 50000
#define N_EDGES 800000
#define HID 512
#define NB_ROW 391            // ceil(50000/128)
#define NB_NODE (NB_ROW * 4)  // 1564 node tiles (6 stages of K=32)
#define NB_UV   (NB_ROW * 8)  // 3128 uv tiles (2 stages of K=32)
#define GRID_GEMM (NB_NODE + NB_UV)
#define NB_EDGE 50000         // 400000 edge pairs / 8 warps per block
#define SMEM_BYTES (4 * 32 * 132 * 4)   // As[2]+Bs[2], 67584 B

typedef unsigned long long ull;

// Scratch (device globals; no allocation allowed)
__device__ __align__(32) __half g_Uh[(size_t)N_NODES * HID];
__device__ __align__(32) __half g_Vh[(size_t)N_NODES * HID];
__device__ __align__(16) float  g_Wc[64 * HID];   // W1 + W2
__device__ __align__(16) float  g_c0[HID];
__device__ __align__(16) float  g_c1[HID];
__device__ int g_idx64;

__device__ __forceinline__ ull dup2(float x) {
    ull r; asm("mov.b64 %0, {%1,%1};" : "=l"(r) : "f"(x)); return r;
}
__device__ __forceinline__ void unpack2(ull p, float& x, float& y) {
    asm("mov.b64 {%0,%1}, %2;" : "=f"(x), "=f"(y) : "l"(p));
}
#define FFMA2(d, a, b, c) \
    asm("fma.rn.f32x2 %0, %1, %2, %3;" : "=l"(d) : "l"(a), "l"(b), "l"(c))

__device__ __forceinline__ void cp16(uint32_t smem, const void* g) {
    asm volatile("cp.async.cg.shared.global [%0], [%1], 16;"
                 :: "r"(smem), "l"(g));
}
#define CP_COMMIT() asm volatile("cp.async.commit_group;")
#define CP_WAIT0()  asm volatile("cp.async.wait_group 0;")

// 256-bit gather load with L2 evict_last (only legal width for the hint).
struct U8 { unsigned r[8]; };
__device__ __forceinline__ U8 ldg256_el(const void* p) {
    U8 v;
    asm("ld.global.nc.L2::evict_last.v8.b32 {%0,%1,%2,%3,%4,%5,%6,%7}, [%8];"
        : "=r"(v.r[0]), "=r"(v.r[1]), "=r"(v.r[2]), "=r"(v.r[3]),
          "=r"(v.r[4]), "=r"(v.r[5]), "=r"(v.r[6]), "=r"(v.r[7])
        : "l"(p));
    return v;
}

// ---------------------------------------------------------------------------
// Prep: blocks 0..31 -> Wc; 32..47 -> c0/c1 (parallel k-reduction);
//       block 48 -> idx64 detect.
// ---------------------------------------------------------------------------
__global__ void prep_kernel(const float* __restrict__ ef,
                            const float* __restrict__ tte,
                            const float* __restrict__ W,
                            const float* __restrict__ b,
                            const int* __restrict__ ei) {
    const int bi = blockIdx.x, tid = threadIdx.x;
    if (bi < 32) {
        int i = bi * 256 + tid;              // 8192 float4
        float4 a = __ldg((const float4*)(W + 128 * HID) + i);
        float4 c = __ldg((const float4*)(W + 192 * HID) + i);
        a.x += c.x; a.y += c.y; a.z += c.z; a.w += c.w;
        ((float4*)g_Wc)[i] = a;
    } else if (bi < 48) {
        __shared__ float sm0[8][32], sm1[8][32];
        const int kc = tid >> 5, jl = tid & 31;
        const int j0 = (bi - 32) * 32;
        const int j = j0 + jl;
        float s0 = 0.f, s1 = 0.f;
        #pragma unroll 4
        for (int k = kc * 16; k < kc * 16 + 16; k++) {
            float w3 = __ldg(&W[(size_t)(256 + k) * HID + j]);
            s0 += tte[k] * w3;
            s1 += tte[128 + k] * w3 + ef[k] * __ldg(&W[(size_t)k * HID + j]);
        }
        sm0[kc][jl] = s0;
        sm1[kc][jl] = s1;
        __syncthreads();
        if (tid < 32) {
            float a0 = b[j0 + tid], a1 = a0;
            #pragma unroll
            for (int q = 0; q < 8; q++) { a0 += sm0[q][tid]; a1 += sm1[q][tid]; }
            g_c0[j0 + tid] = a0;
            g_c1[j0 + tid] = a1;
        }
    } else if (tid == 0) {
        int is64 = 1;
        #pragma unroll
        for (int i = 1; i < 64; i += 2)
            if (ei[i] != 0) is64 = 0;
        g_idx64 = is64;
    }
}

// ---------------------------------------------------------------------------
// Pipelined GEMM. 128x128 tile, BK=32 double-buffered. B streams via
// cp.async (swizzle applied on destination); A is LDG'd into registers one
// stage ahead and STS'd (transposed+swizzled) into the alternate buffer
// after compute, so global latency hides behind the FFMA2 block.
// Read patterns identical to the proven R12 kernel.
// ---------------------------------------------------------------------------
__global__ void __launch_bounds__(256, 2)
gemm_kernel(const float* __restrict__ nf, const float* __restrict__ pe,
            const float* __restrict__ W, float* __restrict__ out) {
    extern __shared__ float smem_dyn[];
    // floats: As0[4224] As1[4224] Bs0[4224] Bs1[4224]  (pitch 132)
    float* AsBuf[2] = { smem_dyn, smem_dyn + 4224 };
    float* BsBuf[2] = { smem_dyn + 8448, smem_dyn + 12672 };
    const uint32_t sbase = (uint32_t)__cvta_generic_to_shared(smem_dyn);

    const int tid = threadIdx.x;
    const int lane_ = tid & 31, wid_ = tid >> 5;
    const int tx8 = (((wid_ & 1) << 3) + (lane_ & 7)) * 8;
    const int ty8 = (((wid_ >> 1) << 2) + (lane_ >> 3)) * 8;
    const int n4a = tx8 >> 2;
    const int n4b = n4a + 1;
    const int swA = (n4a ^ ((n4a >> 3) & 1)) << 4;   // byte offset
    const int swB = (n4b ^ ((n4b >> 3) & 1)) << 4;

    const int bi = blockIdx.x;
    int row0, col0, nstages, is_node, uv = 0;
    if (bi < NB_NODE) {
        is_node = 1;
        row0 = (bi >> 2) * 128;
        col0 = (bi & 3) * 128;
        nstages = 6;
    } else {
        is_node = 0;
        int u = bi - NB_NODE;
        row0 = (u >> 3) * 128;
        uv   = (u & 7) >> 2;
        col0 = (u & 3) * 128;
        nstages = 2;
    }

    // A-loader thread coords (4 chunks): idx=i*256+tid, m=idx>>3, kq=idx&7
    // B cp.async coords (4 chunks): idx=i*256+tid, k=idx>>5, n4=idx&31
    auto lda = [&](int s, float4* regs) {
        const float* Asrc; int L, kcol0;
        if (!is_node)  { Asrc = pe; L = 64;  kcol0 = s * 32; }
        else if (s < 4){ Asrc = nf; L = 128; kcol0 = s * 32; }
        else           { Asrc = pe; L = 64;  kcol0 = (s - 4) * 32; }
        #pragma unroll
        for (int i = 0; i < 4; i++) {
            int idx = i * 256 + tid;
            int m = idx >> 3, kq = idx & 7;
            int r = row0 + m;
            regs[i] = (r < N_NODES)
                ? __ldg((const float4*)(Asrc + (size_t)r * L + kcol0) + kq)
                : make_float4(0.f, 0.f, 0.f, 0.f);
        }
    };
    auto sta = [&](int buf, const float4* regs) {
        float* As = AsBuf[buf];
        #pragma unroll
        for (int i = 0; i < 4; i++) {
            int idx = i * 256 + tid;
            int m = idx >> 3, kq = idx & 7;
            int ms = m ^ (kq << 2);
            As[(kq * 4 + 0) * 132 + ms] = regs[i].x;
            As[(kq * 4 + 1) * 132 + ms] = regs[i].y;
            As[(kq * 4 + 2) * 132 + ms] = regs[i].z;
            As[(kq * 4 + 3) * 132 + ms] = regs[i].w;
        }
    };
    auto ldb = [&](int s, int buf) {
        const float* Bsrc;
        if (!is_node)   Bsrc = W + (size_t)(128 + 64 * uv + s * 32) * HID + col0;
        else if (s < 4) Bsrc = W + (size_t)(s * 32) * HID + col0;
        else            Bsrc = g_Wc + (size_t)((s - 4) * 32) * HID + col0;
        uint32_t bBase = sbase + 33792 + buf * 16896;   // bytes
        #pragma unroll
        for (int i = 0; i < 4; i++) {
            int idx = i * 256 + tid;
            int k = idx >> 5, n4 = idx & 31;
            int n4s = n4 ^ ((n4 >> 3) & 1);
            cp16(bBase + (uint32_t)(k * 528 + n4s * 16),
                 Bsrc + (size_t)k * HID + n4 * 4);
        }
        CP_COMMIT();
    };

    ull acc[32];
    #pragma unroll
    for (int i = 0; i < 32; i++) acc[i] = 0ull;

    float4 aregs[4];
    lda(0, aregs);
    ldb(0, 0);
    sta(0, aregs);
    CP_WAIT0();
    __syncthreads();

    for (int s = 0; s < nstages; s++) {
        const bool more = (s + 1 < nstages);
        if (more) { lda(s + 1, aregs); ldb(s + 1, (s + 1) & 1); }

        const char* bbA = (const char*)BsBuf[s & 1] + swA;
        const char* bbB = (const char*)BsBuf[s & 1] + swB;
        const float* As = AsBuf[s & 1];

        #pragma unroll
        for (int kq = 0; kq < 8; kq++) {
            const int x = kq << 2;
            const float* ar0 = &As[ty8 ^ x];
            const float* ar1 = &As[(ty8 + 4) ^ x];
            #pragma unroll
            for (int kk = 0; kk < 4; kk++) {
                const int k = kq * 4 + kk;
                const float4 a0 = *(const float4*)(ar0 + k * 132);
                const float4 a1 = *(const float4*)(ar1 + k * 132);
                const ulonglong2 B0 = *(const ulonglong2*)(bbA + (size_t)k * 528);
                const ulonglong2 B1 = *(const ulonglong2*)(bbB + (size_t)k * 528);
                ull aa;
                aa = dup2(a0.x);
                FFMA2(acc[ 0], aa, B0.x, acc[ 0]); FFMA2(acc[ 1], aa, B0.y, acc[ 1]);
                FFMA2(acc[ 2], aa, B1.x, acc[ 2]); FFMA2(acc[ 3], aa, B1.y, acc[ 3]);
                aa = dup2(a0.y);
                FFMA2(acc[ 4], aa, B0.x, acc[ 4]); FFMA2(acc[ 5], aa, B0.y, acc[ 5]);
                FFMA2(acc[ 6], aa, B1.x, acc[ 6]); FFMA2(acc[ 7], aa, B1.y, acc[ 7]);
                aa = dup2(a0.z);
                FFMA2(acc[ 8], aa, B0.x, acc[ 8]); FFMA2(acc[ 9], aa, B0.y, acc[ 9]);
                FFMA2(acc[10], aa, B1.x, acc[10]); FFMA2(acc[11], aa, B1.y, acc[11]);
                aa = dup2(a0.w);
                FFMA2(acc[12], aa, B0.x, acc[12]); FFMA2(acc[13], aa, B0.y, acc[13]);
                FFMA2(acc[14], aa, B1.x, acc[14]); FFMA2(acc[15], aa, B1.y, acc[15]);
                aa = dup2(a1.x);
                FFMA2(acc[16], aa, B0.x, acc[16]); FFMA2(acc[17], aa, B0.y, acc[17]);
                FFMA2(acc[18], aa, B1.x, acc[18]); FFMA2(acc[19], aa, B1.y, acc[19]);
                aa = dup2(a1.y);
                FFMA2(acc[20], aa, B0.x, acc[20]); FFMA2(acc[21], aa, B0.y, acc[21]);
                FFMA2(acc[22], aa, B1.x, acc[22]); FFMA2(acc[23], aa, B1.y, acc[23]);
                aa = dup2(a1.z);
                FFMA2(acc[24], aa, B0.x, acc[24]); FFMA2(acc[25], aa, B0.y, acc[25]);
                FFMA2(acc[26], aa, B1.x, acc[26]); FFMA2(acc[27], aa, B1.y, acc[27]);
                aa = dup2(a1.w);
                FFMA2(acc[28], aa, B0.x, acc[28]); FFMA2(acc[29], aa, B0.y, acc[29]);
                FFMA2(acc[30], aa, B1.x, acc[30]); FFMA2(acc[31], aa, B1.y, acc[31]);
            }
        }

        if (more) {
            sta((s + 1) & 1, aregs);
            CP_WAIT0();
            __syncthreads();
        }
    }

    if (!is_node) {
        __half* Out = uv ? g_Vh : g_Uh;
        #pragma unroll
        for (int m = 0; m < 8; m++) {
            int r = row0 + ty8 + m;
            if (r < N_NODES) {
                float f0, f1, f2, f3, f4, f5, f6, f7;
                unpack2(acc[m * 4 + 0], f0, f1);
                unpack2(acc[m * 4 + 1], f2, f3);
                unpack2(acc[m * 4 + 2], f4, f5);
                unpack2(acc[m * 4 + 3], f6, f7);
                uint4 pk;
                __half2* ph = (__half2*)&pk;
                ph[0] = __floats2half2_rn(f0, f1);
                ph[1] = __floats2half2_rn(f2, f3);
                ph[2] = __floats2half2_rn(f4, f5);
                ph[3] = __floats2half2_rn(f6, f7);
                *(uint4*)(Out + (size_t)r * HID + col0 + tx8) = pk;
            }
        }
    } else {
        const float4 cA = *(const float4*)&g_c0[col0 + tx8];
        const float4 cB = *(const float4*)&g_c0[col0 + tx8 + 4];
        #pragma unroll
        for (int m = 0; m < 8; m++) {
            int r = row0 + ty8 + m;
            if (r < N_NODES) {
                float4 o0, o1;
                unpack2(acc[m * 4 + 0], o0.x, o0.y);
                unpack2(acc[m * 4 + 1], o0.z, o0.w);
                unpack2(acc[m * 4 + 2], o1.x, o1.y);
                unpack2(acc[m * 4 + 3], o1.z, o1.w);
                o0.x += cA.x; o0.y += cA.y; o0.z += cA.z; o0.w += cA.w;
                o1.x += cB.x; o1.y += cB.y; o1.z += cB.z; o1.w += cB.w;
                float* dst = out + (size_t)r * HID + col0 + tx8;
                __stcs((float4*)dst, o0);
                __stcs((float4*)(dst + 4), o1);
            }
        }
    }
}

// ---------------------------------------------------------------------------
// Edge rows (R13 measured-best, reverted): one warp per edge pair, LDG.256
// evict_last gathers, smem-swizzled transpose to contiguous 512B store slabs.
// ---------------------------------------------------------------------------
__global__ void __launch_bounds__(256)
edge_kernel(const int* __restrict__ ei, float* __restrict__ out) {
    __shared__ float4 sbuf[8][128];
    const int tid = threadIdx.x;
    const int w = tid >> 5, c = tid & 31;
    const int p = blockIdx.x * 8 + w;
    const int e0 = p * 2, e1 = e0 + 1;

    int s0, d0, s1, d1;
    if (g_idx64) {
        s0 = ei[2 * (size_t)e0];
        d0 = ei[2 * ((size_t)N_EDGES + e0)];
        s1 = ei[2 * (size_t)e1];
        d1 = ei[2 * ((size_t)N_EDGES + e1)];
    } else {
        s0 = ei[e0];  d0 = ei[N_EDGES + e0];
        s1 = ei[e1];  d1 = ei[N_EDGES + e1];
    }

    float4 c1r[4];
    #pragma unroll
    for (int j = 0; j < 4; j++)
        c1r[j] = __ldg((const float4*)g_c1 + c * 4 + j);

    #pragma unroll
    for (int half = 0; half < 2; half++) {
        const int e = half ? e1 : e0;
        const int sI = half ? s1 : s0;
        const int dI = half ? d1 : d0;

        U8 u = ldg256_el(g_Uh + (size_t)sI * HID + c * 16);
        U8 v = ldg256_el(g_Vh + (size_t)dI * HID + c * 16);

        #pragma unroll
        for (int j = 0; j < 4; j++) {
            float2 ua = __half22float2(*(const __half2*)&u.r[j * 2]);
            float2 ub = __half22float2(*(const __half2*)&u.r[j * 2 + 1]);
            float2 va = __half22float2(*(const __half2*)&v.r[j * 2]);
            float2 vb = __half22float2(*(const __half2*)&v.r[j * 2 + 1]);
            float4 o;
            o.x = ua.x + va.x + c1r[j].x;  o.y = ua.y + va.y + c1r[j].y;
            o.z = ub.x + vb.x + c1r[j].z;  o.w = ub.y + vb.y + c1r[j].w;
            int g = c * 4 + j;
            sbuf[w][g ^ (g >> 2)] = o;
        }
        __syncwarp();

        float4* dst = (float4*)(out + (size_t)(N_NODES + e) * HID);
        #pragma unroll
        for (int q = 0; q < 4; q++) {
            int h = q * 32 + c;
            float4 val = sbuf[w][h ^ (h >> 2)];
            __stcs(dst + h, val);
        }
        __syncwarp();
    }
}

// ---------------------------------------------------------------------------
static bool g_attr_set = false;

extern "C" void kernel_launch(void* const* d_in, const int* in_sizes, int n_in,
                              void* d_out, int out_size) {
    const void* ptr[7] = {d_in[0], d_in[1], d_in[2], d_in[3], d_in[4], d_in[5], d_in[6]};
    const int want[7] = {6400000, 3200000, 128, 256, 196608, 512, 1600000};
    const void* mapped[7];
    for (int w = 0; w < 7; w++) {
        mapped[w] = ptr[w < n_in ? w : 0];
        for (int i = 0; i < n_in && i < 7; i++)
            if (in_sizes[i] == want[w]) { mapped[w] = ptr[i]; break; }
    }
    const float* nf  = (const float*)mapped[0];
    const float* pe  = (const float*)mapped[1];
    const float* ef  = (const float*)mapped[2];
    const float* tte = (const float*)mapped[3];
    const float* W   = (const float*)mapped[4];
    const float* b   = (const float*)mapped[5];
    const int*   ei  = (const int*)mapped[6];
    float* out = (float*)d_out;

    if (!g_attr_set) {
        cudaStreamCaptureStatus cs = cudaStreamCaptureStatusNone;
        cudaStreamIsCapturing((cudaStream_t)0, &cs);
        if (cs == cudaStreamCaptureStatusNone) {
            cudaFuncSetAttribute(gemm_kernel,
                                 cudaFuncAttributeMaxDynamicSharedMemorySize,
                                 SMEM_BYTES);
            g_attr_set = true;
        }
    }

    prep_kernel<<<49, 256>>>(ef, tte, W, b, ei);
    gemm_kernel<<<GRID_GEMM, 256, SMEM_BYTES>>>(nf, pe, W, out);
    edge_kernel<<<NB_EDGE, 256>>>(ei, out);
}